// round 10
// baseline (speedup 1.0000x reference)
#include <cuda_runtime.h>
#include <cuda_bf16.h>
#include <math.h>

#define NN    100000
#define NPAD  100096      // 391 * 256
#define EE    1250000
#define RR    16
#define DD    64
#define SCANB (NPAD / 256)   // 391
#define WCVTB 256            // RR*DD*DD/256 blocks for W conversion

// ---------------- static device scratch (no allocs allowed) ----------------
__device__ __nv_bfloat16 g_Wbf[RR * DD * DD];            // Wt[r][j][d] = W[r][d][j]
__device__ __nv_bfloat16 g_Tall[(size_t)RR * NPAD * DD]; // [rel][node][64] bf16
__device__ int2          g_pair[EE];                     // CSR-ordered (tail, etype)
__device__ int           g_rowstart[NN + 2];
__device__ int           g_cursor[NN];
__device__ int           g_cnt[NN];          // zero at entry (static init / fused cleanup)
__device__ int           g_bsum[SCANB + 1];

// ---------------- W transpose + cvt (tiny; unblocks the GEMM fork) ----------------
__global__ void __launch_bounds__(256) k_wcvt(const float* __restrict__ W) {
    int idx = blockIdx.x * 256 + threadIdx.x;
    int r = idx >> 12, rem = idx & 4095;
    int j = rem >> 6, d = rem & 63;
    g_Wbf[idx] = __float2bfloat16(W[(r << 12) + d * DD + j]);
}

// ---------------- hist (counts only; no rmask anymore) ----------------
__global__ void k_hist(const int* __restrict__ head, int E) {
    int e = blockIdx.x * blockDim.x + threadIdx.x;
    if (e < E) atomicAdd(&g_cnt[head[e]], 1);
}

// ---------------- scan phase 1: per-block sums ----------------
__global__ void k_scan1(int N) {
    __shared__ int sh[8];
    int b = blockIdx.x, t = threadIdx.x;
    int i = b * 256 + t;
    int v = (i < N) ? g_cnt[i] : 0;
    int x = v;
    #pragma unroll
    for (int o = 16; o; o >>= 1) x += __shfl_xor_sync(0xffffffffu, x, o);
    if ((t & 31) == 0) sh[t >> 5] = x;
    __syncthreads();
    if (t == 0) {
        int s = 0;
        #pragma unroll
        for (int q = 0; q < 8; q++) s += sh[q];
        g_bsum[b] = s;
    }
}

// ---------------- scan phase 2+3 merged ----------------
__global__ void k_scan23(int N, int E) {
    __shared__ int red[8];
    __shared__ int wsum[8];
    __shared__ int boff_sh;
    int b = blockIdx.x, t = threadIdx.x;

    int part = 0;
    for (int j = t; j < b; j += 256) part += g_bsum[j];
    #pragma unroll
    for (int o = 16; o; o >>= 1) part += __shfl_xor_sync(0xffffffffu, part, o);
    if ((t & 31) == 0) red[t >> 5] = part;
    __syncthreads();
    if (t == 0) {
        int s = 0;
        #pragma unroll
        for (int q = 0; q < 8; q++) s += red[q];
        boff_sh = s;
    }
    __syncthreads();
    int boff = boff_sh;

    int i = b * 256 + t;
    int v = (i < N) ? g_cnt[i] : 0;
    int x = v;
    #pragma unroll
    for (int o = 1; o < 32; o <<= 1) {
        int y = __shfl_up_sync(0xffffffffu, x, o);
        if ((t & 31) >= o) x += y;
    }
    if ((t & 31) == 31) wsum[t >> 5] = x;
    __syncthreads();
    if (t < 8) {
        int s = wsum[t], xs = s;
        #pragma unroll
        for (int o = 1; o < 8; o <<= 1) {
            int y = __shfl_up_sync(0xffu, xs, o);
            if (t >= o) xs += y;
        }
        wsum[t] = xs - s;
    }
    __syncthreads();
    int excl = (x - v) + wsum[t >> 5] + boff;
    if (i <= N) g_rowstart[i] = (i == N) ? E : excl;
    if (i < N)  g_cursor[i] = excl;
}

// ---------------- CSR fill ----------------
__global__ void k_fill(const int* __restrict__ head, const int* __restrict__ tail,
                       const int* __restrict__ etype, int E) {
    int e = blockIdx.x * blockDim.x + threadIdx.x;
    if (e < E) {
        int pos = atomicAdd(&g_cursor[head[e]], 1);
        g_pair[pos] = make_int2(tail[e], etype[e]);
    }
}

// ---------------- GEMM: A-reuse over all 16 relations, unmasked stores ----------
__global__ void __launch_bounds__(256) k_gemm(const float* __restrict__ ego, int N) {
    __shared__ __nv_bfloat16 sW[DD * DD];
    int bx = blockIdx.x;
    int warp = threadIdx.x >> 5, lane = threadIdx.x & 31;
    int g = lane >> 2, t = lane & 3;
    int base = bx * 256 + warp * 32;

    // preload A fragments once from fp32 ego (convert in registers, pad rows = 0)
    unsigned afrag[4][2][4];
    #pragma unroll
    for (int ks = 0; ks < 4; ks++) {
        int k0 = ks * 16;
        #pragma unroll
        for (int mt = 0; mt < 2; mt++) {
            int r0 = base + mt * 16 + g;
            int r1 = r0 + 8;
            #pragma unroll
            for (int half = 0; half < 2; half++) {
                int col = k0 + 2 * t + half * 8;
                float2 f0 = (r0 < N) ? *(const float2*)(ego + (size_t)r0 * DD + col)
                                     : make_float2(0.f, 0.f);
                float2 f1 = (r1 < N) ? *(const float2*)(ego + (size_t)r1 * DD + col)
                                     : make_float2(0.f, 0.f);
                __nv_bfloat162 h0 = __floats2bfloat162_rn(f0.x, f0.y);
                __nv_bfloat162 h1 = __floats2bfloat162_rn(f1.x, f1.y);
                afrag[ks][mt][half * 2]     = *(unsigned*)&h0;
                afrag[ks][mt][half * 2 + 1] = *(unsigned*)&h1;
            }
        }
    }

    for (int r = 0; r < RR; r++) {
        __syncthreads();   // previous relation's MMAs done before overwriting sW
        const float4* src = (const float4*)(g_Wbf + (r << 12));
        float4* dst = (float4*)sW;
        for (int i = threadIdx.x; i < DD * DD / 8; i += 256) dst[i] = src[i];
        __syncthreads();

        float acc[2][8][4];
        #pragma unroll
        for (int i = 0; i < 2; i++)
            #pragma unroll
            for (int j = 0; j < 8; j++)
                #pragma unroll
                for (int q = 0; q < 4; q++) acc[i][j][q] = 0.0f;

        #pragma unroll
        for (int ks = 0; ks < 4; ks++) {
            int k0 = ks * 16;
            #pragma unroll
            for (int nt = 0; nt < 8; nt++) {
                const unsigned* q = (const unsigned*)(sW + (nt * 8 + g) * DD + k0 + 2 * t);
                unsigned b0 = q[0], b1 = q[4];
                #pragma unroll
                for (int mt = 0; mt < 2; mt++) {
                    asm volatile(
                        "mma.sync.aligned.m16n8k16.row.col.f32.bf16.bf16.f32 "
                        "{%0,%1,%2,%3}, {%4,%5,%6,%7}, {%8,%9}, {%0,%1,%2,%3};"
                        : "+f"(acc[mt][nt][0]), "+f"(acc[mt][nt][1]),
                          "+f"(acc[mt][nt][2]), "+f"(acc[mt][nt][3])
                        : "r"(afrag[ks][mt][0]), "r"(afrag[ks][mt][1]),
                          "r"(afrag[ks][mt][2]), "r"(afrag[ks][mt][3]),
                          "r"(b0), "r"(b1));
                }
            }
        }
        __nv_bfloat16* T = g_Tall + (size_t)r * NPAD * DD;
        #pragma unroll
        for (int nt = 0; nt < 8; nt++) {
            int col = nt * 8 + 2 * t;
            __nv_bfloat162 h0 = __floats2bfloat162_rn(acc[0][nt][0], acc[0][nt][1]);
            __nv_bfloat162 h1 = __floats2bfloat162_rn(acc[0][nt][2], acc[0][nt][3]);
            __nv_bfloat162 h2 = __floats2bfloat162_rn(acc[1][nt][0], acc[1][nt][1]);
            __nv_bfloat162 h3 = __floats2bfloat162_rn(acc[1][nt][2], acc[1][nt][3]);
            int row0 = base + g;
            *(unsigned*)(T + (size_t)row0 * DD + col)        = *(unsigned*)&h0;
            *(unsigned*)(T + (size_t)(row0 + 8) * DD + col)  = *(unsigned*)&h1;
            *(unsigned*)(T + (size_t)(row0 + 16) * DD + col) = *(unsigned*)&h2;
            *(unsigned*)(T + (size_t)(row0 + 24) * DD + col) = *(unsigned*)&h3;
        }
    }
}

// ---------------- fused pass: 4 independent nodes per warp, 8 lanes each ----------------
__global__ void __launch_bounds__(256) k_fused(const float* __restrict__ ego,
                                               float* __restrict__ out, int N) {
    int warpid = (blockIdx.x * blockDim.x + threadIdx.x) >> 5;
    int lane = threadIdx.x & 31;
    int node = warpid * 4 + (lane >> 3);     // each 8-lane group owns one node
    int q = lane & 7;                         // dims q*8 .. q*8+7
    unsigned gm = 0xFFu << (lane & 24);       // this group's shuffle mask
    if (node >= N) return;
    if (q == 0) g_cnt[node] = 0;              // restore zero-at-entry

    int s = g_rowstart[node], en = g_rowstart[node + 1];
    int cnt = en - s;

    const __nv_bfloat16* Trow = g_Tall + (size_t)node * DD + 8 * q;  // + r*NPAD*DD
    float4 acA = make_float4(0.f, 0.f, 0.f, 0.f);
    float4 acB = make_float4(0.f, 0.f, 0.f, 0.f);
    float den = 0.0f;

    int i = s;
    // parity peel so the main loop's pair loads are 16B-aligned int4
    if ((i & 1) && i < en) {
        int2 pe = g_pair[i];
        uint4 t0 = *(const uint4*)(Trow + (size_t)pe.y * NPAD * DD);
        const float4* vp0 = (const float4*)(ego + (size_t)pe.x * DD + 8 * q);
        float4 v0a = vp0[0], v0b = vp0[1];
        float2 a00 = __bfloat1622float2(*(__nv_bfloat162*)&t0.x);
        float2 a01 = __bfloat1622float2(*(__nv_bfloat162*)&t0.y);
        float2 a02 = __bfloat1622float2(*(__nv_bfloat162*)&t0.z);
        float2 a03 = __bfloat1622float2(*(__nv_bfloat162*)&t0.w);
        float d0 = fmaf(a00.x, v0a.x, a00.y * v0a.y);
        d0 = fmaf(a01.x, v0a.z, d0); d0 = fmaf(a01.y, v0a.w, d0);
        d0 = fmaf(a02.x, v0b.x, d0); d0 = fmaf(a02.y, v0b.y, d0);
        d0 = fmaf(a03.x, v0b.z, d0); d0 = fmaf(a03.y, v0b.w, d0);
        #pragma unroll
        for (int o = 4; o; o >>= 1) d0 += __shfl_xor_sync(gm, d0, o);
        float e0 = __expf(d0 < 0.0f ? 0.01f * d0 : d0);
        acA.x = fmaf(e0, v0a.x, acA.x); acA.y = fmaf(e0, v0a.y, acA.y);
        acA.z = fmaf(e0, v0a.z, acA.z); acA.w = fmaf(e0, v0a.w, acA.w);
        acB.x = fmaf(e0, v0b.x, acB.x); acB.y = fmaf(e0, v0b.y, acB.y);
        acB.z = fmaf(e0, v0b.z, acB.z); acB.w = fmaf(e0, v0b.w, acB.w);
        den += e0;
        i++;
    }
    for (; i + 1 < en; i += 2) {
        int4 pp = *(const int4*)&g_pair[i];   // (tail0, rel0, tail1, rel1)
        uint4 t0 = *(const uint4*)(Trow + (size_t)pp.y * NPAD * DD);
        uint4 t1 = *(const uint4*)(Trow + (size_t)pp.w * NPAD * DD);
        const float4* vp0 = (const float4*)(ego + (size_t)pp.x * DD + 8 * q);
        const float4* vp1 = (const float4*)(ego + (size_t)pp.z * DD + 8 * q);
        float4 v0a = vp0[0], v0b = vp0[1];
        float4 v1a = vp1[0], v1b = vp1[1];
        float2 a00 = __bfloat1622float2(*(__nv_bfloat162*)&t0.x);
        float2 a01 = __bfloat1622float2(*(__nv_bfloat162*)&t0.y);
        float2 a02 = __bfloat1622float2(*(__nv_bfloat162*)&t0.z);
        float2 a03 = __bfloat1622float2(*(__nv_bfloat162*)&t0.w);
        float2 a10 = __bfloat1622float2(*(__nv_bfloat162*)&t1.x);
        float2 a11 = __bfloat1622float2(*(__nv_bfloat162*)&t1.y);
        float2 a12 = __bfloat1622float2(*(__nv_bfloat162*)&t1.z);
        float2 a13 = __bfloat1622float2(*(__nv_bfloat162*)&t1.w);
        float d0 = fmaf(a00.x, v0a.x, a00.y * v0a.y);
        d0 = fmaf(a01.x, v0a.z, d0); d0 = fmaf(a01.y, v0a.w, d0);
        d0 = fmaf(a02.x, v0b.x, d0); d0 = fmaf(a02.y, v0b.y, d0);
        d0 = fmaf(a03.x, v0b.z, d0); d0 = fmaf(a03.y, v0b.w, d0);
        float d1 = fmaf(a10.x, v1a.x, a10.y * v1a.y);
        d1 = fmaf(a11.x, v1a.z, d1); d1 = fmaf(a11.y, v1a.w, d1);
        d1 = fmaf(a12.x, v1b.x, d1); d1 = fmaf(a12.y, v1b.y, d1);
        d1 = fmaf(a13.x, v1b.z, d1); d1 = fmaf(a13.y, v1b.w, d1);
        #pragma unroll
        for (int o = 4; o; o >>= 1) {
            d0 += __shfl_xor_sync(gm, d0, o);
            d1 += __shfl_xor_sync(gm, d1, o);
        }
        float e0 = __expf(d0 < 0.0f ? 0.01f * d0 : d0);
        float e1 = __expf(d1 < 0.0f ? 0.01f * d1 : d1);
        acA.x = fmaf(e0, v0a.x, acA.x); acA.y = fmaf(e0, v0a.y, acA.y);
        acA.z = fmaf(e0, v0a.z, acA.z); acA.w = fmaf(e0, v0a.w, acA.w);
        acB.x = fmaf(e0, v0b.x, acB.x); acB.y = fmaf(e0, v0b.y, acB.y);
        acB.z = fmaf(e0, v0b.z, acB.z); acB.w = fmaf(e0, v0b.w, acB.w);
        acA.x = fmaf(e1, v1a.x, acA.x); acA.y = fmaf(e1, v1a.y, acA.y);
        acA.z = fmaf(e1, v1a.z, acA.z); acA.w = fmaf(e1, v1a.w, acA.w);
        acB.x = fmaf(e1, v1b.x, acB.x); acB.y = fmaf(e1, v1b.y, acB.y);
        acB.z = fmaf(e1, v1b.z, acB.z); acB.w = fmaf(e1, v1b.w, acB.w);
        den += e0 + e1;
    }
    if (i < en) {
        int2 pe = g_pair[i];
        uint4 t0 = *(const uint4*)(Trow + (size_t)pe.y * NPAD * DD);
        const float4* vp0 = (const float4*)(ego + (size_t)pe.x * DD + 8 * q);
        float4 v0a = vp0[0], v0b = vp0[1];
        float2 a00 = __bfloat1622float2(*(__nv_bfloat162*)&t0.x);
        float2 a01 = __bfloat1622float2(*(__nv_bfloat162*)&t0.y);
        float2 a02 = __bfloat1622float2(*(__nv_bfloat162*)&t0.z);
        float2 a03 = __bfloat1622float2(*(__nv_bfloat162*)&t0.w);
        float d0 = fmaf(a00.x, v0a.x, a00.y * v0a.y);
        d0 = fmaf(a01.x, v0a.z, d0); d0 = fmaf(a01.y, v0a.w, d0);
        d0 = fmaf(a02.x, v0b.x, d0); d0 = fmaf(a02.y, v0b.y, d0);
        d0 = fmaf(a03.x, v0b.z, d0); d0 = fmaf(a03.y, v0b.w, d0);
        #pragma unroll
        for (int o = 4; o; o >>= 1) d0 += __shfl_xor_sync(gm, d0, o);
        float e0 = __expf(d0 < 0.0f ? 0.01f * d0 : d0);
        acA.x = fmaf(e0, v0a.x, acA.x); acA.y = fmaf(e0, v0a.y, acA.y);
        acA.z = fmaf(e0, v0a.z, acA.z); acA.w = fmaf(e0, v0a.w, acA.w);
        acB.x = fmaf(e0, v0b.x, acB.x); acB.y = fmaf(e0, v0b.y, acB.y);
        acB.z = fmaf(e0, v0b.z, acB.z); acB.w = fmaf(e0, v0b.w, acB.w);
        den += e0;
    }

    float sc = cnt > 0 ? 1.0f / (den * (float)cnt) : 0.0f;
    float4* op = (float4*)(out + (size_t)node * DD + 8 * q);
    op[0] = make_float4(acA.x * sc, acA.y * sc, acA.z * sc, acA.w * sc);
    op[1] = make_float4(acB.x * sc, acB.y * sc, acB.z * sc, acB.w * sc);
}

// ---------------- launch: fork GEMM immediately after tiny W-cvt ----------------
extern "C" void kernel_launch(void* const* d_in, const int* in_sizes, int n_in,
                              void* d_out, int out_size) {
    const float* ego   = (const float*)d_in[0];
    const float* W     = (const float*)d_in[1];
    const int*   eidx  = (const int*)d_in[2];
    const int*   etype = (const int*)d_in[3];
    int N = in_sizes[0] / DD;
    int E = in_sizes[3];
    const int* head = eidx;
    const int* tail = eidx + E;
    float* out = (float*)d_out;

    // host-side resources created once (no device memory involved)
    static cudaStream_t s1 = nullptr;
    static cudaEvent_t evFork = nullptr, evJoin = nullptr;
    if (!s1) {
        cudaStreamCreateWithFlags(&s1, cudaStreamNonBlocking);
        cudaEventCreateWithFlags(&evFork, cudaEventDisableTiming);
        cudaEventCreateWithFlags(&evJoin, cudaEventDisableTiming);
    }

    int histb = (E + 255) / 256;

    k_wcvt<<<WCVTB, 256>>>(W);

    // fork: GEMM needs only g_Wbf — runs concurrently with hist/scans/fill
    cudaEventRecord(evFork, 0);
    cudaStreamWaitEvent(s1, evFork, 0);
    k_gemm<<<SCANB, 256, 0, s1>>>(ego, N);
    cudaEventRecord(evJoin, s1);

    k_hist<<<histb, 256>>>(head, E);
    k_scan1<<<SCANB, 256>>>(N);
    k_scan23<<<SCANB, 256>>>(N, E);
    k_fill<<<histb, 256>>>(head, tail, etype, E);

    // join: fused needs both the CSR (stream 0) and T_all (s1)
    cudaStreamWaitEvent(0, evJoin, 0);
    int warps = (N + 3) / 4;
    k_fused<<<(warps * 32 + 255) / 256, 256>>>(ego, out, N);
}

// round 11
// speedup vs baseline: 1.0432x; 1.0432x over previous
#include <cuda_runtime.h>
#include <cuda_bf16.h>
#include <math.h>

#define NN    100000
#define NPAD  100096      // 391 * 256
#define EE    1250000
#define RR    16
#define DD    64
#define SCANB (NPAD / 256)   // 391
#define WCVTB 256            // RR*DD*DD/256 blocks for W conversion

// ---------------- static device scratch (no allocs allowed) ----------------
__device__ __nv_bfloat16 g_Wbf[RR * DD * DD];            // Wt[r][j][d] = W[r][d][j]
__device__ __nv_bfloat16 g_Tall[(size_t)RR * NPAD * DD]; // [rel][node][64] bf16
__device__ int2          g_pair[EE];                     // CSR-ordered (tail, etype)
__device__ int           g_rowstart[NN + 2];
__device__ int           g_cursor[NN];
__device__ int           g_cnt[NN];          // zero at entry (static init / fused cleanup)
__device__ int           g_rmask[NPAD];      // per-node used-relation bitmask, same contract
__device__ int           g_bsum[SCANB + 1];

// ---------------- combo1: {W transpose+cvt} ∪ {hist + relation mask, 4 edges/thread} ----
__global__ void __launch_bounds__(256) k_combo1(const float* __restrict__ W,
                                                const int* __restrict__ head,
                                                const int* __restrict__ etype,
                                                int E) {
    int bx = blockIdx.x;
    if (bx < WCVTB) {
        int idx = bx * 256 + threadIdx.x;
        int r = idx >> 12, rem = idx & 4095;
        int j = rem >> 6, d = rem & 63;
        g_Wbf[idx] = __float2bfloat16(W[(r << 12) + d * DD + j]);
    } else {
        int e0 = ((bx - WCVTB) * 256 + threadIdx.x) * 4;
        if (e0 + 3 < E) {
            int4 h4 = *(const int4*)(head + e0);
            int4 t4 = *(const int4*)(etype + e0);
            atomicAdd(&g_cnt[h4.x], 1);  atomicOr(&g_rmask[h4.x], 1 << t4.x);
            atomicAdd(&g_cnt[h4.y], 1);  atomicOr(&g_rmask[h4.y], 1 << t4.y);
            atomicAdd(&g_cnt[h4.z], 1);  atomicOr(&g_rmask[h4.z], 1 << t4.z);
            atomicAdd(&g_cnt[h4.w], 1);  atomicOr(&g_rmask[h4.w], 1 << t4.w);
        } else {
            for (int e = e0; e < E; e++) {
                int h = head[e];
                atomicAdd(&g_cnt[h], 1);
                atomicOr(&g_rmask[h], 1 << etype[e]);
            }
        }
    }
}

// ---------------- scan phase 1: per-block sums ----------------
__global__ void k_scan1(int N) {
    __shared__ int sh[8];
    int b = blockIdx.x, t = threadIdx.x;
    int i = b * 256 + t;
    int v = (i < N) ? g_cnt[i] : 0;
    int x = v;
    #pragma unroll
    for (int o = 16; o; o >>= 1) x += __shfl_xor_sync(0xffffffffu, x, o);
    if ((t & 31) == 0) sh[t >> 5] = x;
    __syncthreads();
    if (t == 0) {
        int s = 0;
        #pragma unroll
        for (int q = 0; q < 8; q++) s += sh[q];
        g_bsum[b] = s;
    }
}

// ---------------- scan phase 2+3 merged ----------------
__global__ void k_scan23(int N, int E) {
    __shared__ int red[8];
    __shared__ int wsum[8];
    __shared__ int boff_sh;
    int b = blockIdx.x, t = threadIdx.x;

    int part = 0;
    for (int j = t; j < b; j += 256) part += g_bsum[j];
    #pragma unroll
    for (int o = 16; o; o >>= 1) part += __shfl_xor_sync(0xffffffffu, part, o);
    if ((t & 31) == 0) red[t >> 5] = part;
    __syncthreads();
    if (t == 0) {
        int s = 0;
        #pragma unroll
        for (int q = 0; q < 8; q++) s += red[q];
        boff_sh = s;
    }
    __syncthreads();
    int boff = boff_sh;

    int i = b * 256 + t;
    int v = (i < N) ? g_cnt[i] : 0;
    int x = v;
    #pragma unroll
    for (int o = 1; o < 32; o <<= 1) {
        int y = __shfl_up_sync(0xffffffffu, x, o);
        if ((t & 31) >= o) x += y;
    }
    if ((t & 31) == 31) wsum[t >> 5] = x;
    __syncthreads();
    if (t < 8) {
        int s = wsum[t], xs = s;
        #pragma unroll
        for (int o = 1; o < 8; o <<= 1) {
            int y = __shfl_up_sync(0xffu, xs, o);
            if (t >= o) xs += y;
        }
        wsum[t] = xs - s;
    }
    __syncthreads();
    int excl = (x - v) + wsum[t >> 5] + boff;
    if (i <= N) g_rowstart[i] = (i == N) ? E : excl;
    if (i < N)  g_cursor[i] = excl;
}

// ---------------- CSR fill ----------------
__global__ void k_fill(const int* __restrict__ head, const int* __restrict__ tail,
                       const int* __restrict__ etype, int E) {
    int e = blockIdx.x * blockDim.x + threadIdx.x;
    if (e < E) {
        int pos = atomicAdd(&g_cursor[head[e]], 1);
        g_pair[pos] = make_int2(tail[e], etype[e]);
    }
}

// ---------------- GEMM: A-reuse, masked stores, double-buffered W ----------
__global__ void __launch_bounds__(256) k_gemm(const float* __restrict__ ego, int N) {
    __shared__ __nv_bfloat16 sW[2][DD * DD];
    int bx = blockIdx.x;
    int warp = threadIdx.x >> 5, lane = threadIdx.x & 31;
    int g = lane >> 2, t = lane & 3;
    int base = bx * 256 + warp * 32;

    // preload A fragments once from fp32 ego (convert in registers, pad rows = 0)
    unsigned afrag[4][2][4];
    #pragma unroll
    for (int ks = 0; ks < 4; ks++) {
        int k0 = ks * 16;
        #pragma unroll
        for (int mt = 0; mt < 2; mt++) {
            int r0 = base + mt * 16 + g;
            int r1 = r0 + 8;
            #pragma unroll
            for (int half = 0; half < 2; half++) {
                int col = k0 + 2 * t + half * 8;
                float2 f0 = (r0 < N) ? *(const float2*)(ego + (size_t)r0 * DD + col)
                                     : make_float2(0.f, 0.f);
                float2 f1 = (r1 < N) ? *(const float2*)(ego + (size_t)r1 * DD + col)
                                     : make_float2(0.f, 0.f);
                __nv_bfloat162 h0 = __floats2bfloat162_rn(f0.x, f0.y);
                __nv_bfloat162 h1 = __floats2bfloat162_rn(f1.x, f1.y);
                afrag[ks][mt][half * 2]     = *(unsigned*)&h0;
                afrag[ks][mt][half * 2 + 1] = *(unsigned*)&h1;
            }
        }
    }
    int rm0 = g_rmask[base + g];
    int rm1 = g_rmask[base + g + 8];
    int rm2 = g_rmask[base + 16 + g];
    int rm3 = g_rmask[base + 24 + g];

    // stage W[0] into buffer 0
    {
        const float4* src = (const float4*)(g_Wbf);
        float4* dst = (float4*)sW[0];
        for (int i = threadIdx.x; i < DD * DD / 8; i += 256) dst[i] = src[i];
    }
    __syncthreads();

    for (int r = 0; r < RR; r++) {
        int cur = r & 1;
        // prefetch next relation's W into the other buffer (overlaps MMAs)
        if (r + 1 < RR) {
            const float4* src = (const float4*)(g_Wbf + ((r + 1) << 12));
            float4* dst = (float4*)sW[cur ^ 1];
            for (int i = threadIdx.x; i < DD * DD / 8; i += 256) dst[i] = src[i];
        }

        float acc[2][8][4];
        #pragma unroll
        for (int i = 0; i < 2; i++)
            #pragma unroll
            for (int j = 0; j < 8; j++)
                #pragma unroll
                for (int q = 0; q < 4; q++) acc[i][j][q] = 0.0f;

        #pragma unroll
        for (int ks = 0; ks < 4; ks++) {
            int k0 = ks * 16;
            #pragma unroll
            for (int nt = 0; nt < 8; nt++) {
                const unsigned* q = (const unsigned*)(sW[cur] + (nt * 8 + g) * DD + k0 + 2 * t);
                unsigned b0 = q[0], b1 = q[4];
                #pragma unroll
                for (int mt = 0; mt < 2; mt++) {
                    asm volatile(
                        "mma.sync.aligned.m16n8k16.row.col.f32.bf16.bf16.f32 "
                        "{%0,%1,%2,%3}, {%4,%5,%6,%7}, {%8,%9}, {%0,%1,%2,%3};"
                        : "+f"(acc[mt][nt][0]), "+f"(acc[mt][nt][1]),
                          "+f"(acc[mt][nt][2]), "+f"(acc[mt][nt][3])
                        : "r"(afrag[ks][mt][0]), "r"(afrag[ks][mt][1]),
                          "r"(afrag[ks][mt][2]), "r"(afrag[ks][mt][3]),
                          "r"(b0), "r"(b1));
                }
            }
        }
        __nv_bfloat16* T = g_Tall + (size_t)r * NPAD * DD;
        bool use0 = (rm0 >> r) & 1, use1 = (rm1 >> r) & 1;
        bool use2 = (rm2 >> r) & 1, use3 = (rm3 >> r) & 1;
        #pragma unroll
        for (int nt = 0; nt < 8; nt++) {
            int col = nt * 8 + 2 * t;
            __nv_bfloat162 h0 = __floats2bfloat162_rn(acc[0][nt][0], acc[0][nt][1]);
            __nv_bfloat162 h1 = __floats2bfloat162_rn(acc[0][nt][2], acc[0][nt][3]);
            __nv_bfloat162 h2 = __floats2bfloat162_rn(acc[1][nt][0], acc[1][nt][1]);
            __nv_bfloat162 h3 = __floats2bfloat162_rn(acc[1][nt][2], acc[1][nt][3]);
            int row0 = base + g;
            if (use0) *(unsigned*)(T + (size_t)row0 * DD + col)        = *(unsigned*)&h0;
            if (use1) *(unsigned*)(T + (size_t)(row0 + 8) * DD + col)  = *(unsigned*)&h1;
            if (use2) *(unsigned*)(T + (size_t)(row0 + 16) * DD + col) = *(unsigned*)&h2;
            if (use3) *(unsigned*)(T + (size_t)(row0 + 24) * DD + col) = *(unsigned*)&h3;
        }
        __syncthreads();   // MMA reads of sW[cur] done before it's restaged at r+1
    }
}

// ---------------- fused pass: 4 independent nodes per warp, 8 lanes each (FROZEN) ------
__global__ void __launch_bounds__(256) k_fused(const float* __restrict__ ego,
                                               float* __restrict__ out, int N) {
    int warpid = (blockIdx.x * blockDim.x + threadIdx.x) >> 5;
    int lane = threadIdx.x & 31;
    int node = warpid * 4 + (lane >> 3);     // each 8-lane group owns one node
    int q = lane & 7;                         // dims q*8 .. q*8+7
    unsigned gm = 0xFFu << (lane & 24);       // this group's shuffle mask
    if (node >= N) return;
    if (q == 0) { g_cnt[node] = 0; g_rmask[node] = 0; }  // restore zero-at-entry

    int s = g_rowstart[node], en = g_rowstart[node + 1];
    int cnt = en - s;

    const __nv_bfloat16* Trow = g_Tall + (size_t)node * DD + 8 * q;  // + r*NPAD*DD
    float4 acA = make_float4(0.f, 0.f, 0.f, 0.f);
    float4 acB = make_float4(0.f, 0.f, 0.f, 0.f);
    float den = 0.0f;

    int i = s;
    for (; i + 1 < en; i += 2) {
        int2 pe0 = g_pair[i];
        int2 pe1 = g_pair[i + 1];
        uint4 t0 = *(const uint4*)(Trow + (size_t)pe0.y * NPAD * DD);
        uint4 t1 = *(const uint4*)(Trow + (size_t)pe1.y * NPAD * DD);
        const float4* vp0 = (const float4*)(ego + (size_t)pe0.x * DD + 8 * q);
        const float4* vp1 = (const float4*)(ego + (size_t)pe1.x * DD + 8 * q);
        float4 v0a = vp0[0], v0b = vp0[1];
        float4 v1a = vp1[0], v1b = vp1[1];
        float2 a00 = __bfloat1622float2(*(__nv_bfloat162*)&t0.x);
        float2 a01 = __bfloat1622float2(*(__nv_bfloat162*)&t0.y);
        float2 a02 = __bfloat1622float2(*(__nv_bfloat162*)&t0.z);
        float2 a03 = __bfloat1622float2(*(__nv_bfloat162*)&t0.w);
        float2 a10 = __bfloat1622float2(*(__nv_bfloat162*)&t1.x);
        float2 a11 = __bfloat1622float2(*(__nv_bfloat162*)&t1.y);
        float2 a12 = __bfloat1622float2(*(__nv_bfloat162*)&t1.z);
        float2 a13 = __bfloat1622float2(*(__nv_bfloat162*)&t1.w);
        float d0 = fmaf(a00.x, v0a.x, a00.y * v0a.y);
        d0 = fmaf(a01.x, v0a.z, d0); d0 = fmaf(a01.y, v0a.w, d0);
        d0 = fmaf(a02.x, v0b.x, d0); d0 = fmaf(a02.y, v0b.y, d0);
        d0 = fmaf(a03.x, v0b.z, d0); d0 = fmaf(a03.y, v0b.w, d0);
        float d1 = fmaf(a10.x, v1a.x, a10.y * v1a.y);
        d1 = fmaf(a11.x, v1a.z, d1); d1 = fmaf(a11.y, v1a.w, d1);
        d1 = fmaf(a12.x, v1b.x, d1); d1 = fmaf(a12.y, v1b.y, d1);
        d1 = fmaf(a13.x, v1b.z, d1); d1 = fmaf(a13.y, v1b.w, d1);
        #pragma unroll
        for (int o = 4; o; o >>= 1) {
            d0 += __shfl_xor_sync(gm, d0, o);
            d1 += __shfl_xor_sync(gm, d1, o);
        }
        float s0 = d0 < 0.0f ? 0.01f * d0 : d0;
        float s1 = d1 < 0.0f ? 0.01f * d1 : d1;
        float e0 = __expf(s0);
        float e1 = __expf(s1);
        acA.x = fmaf(e0, v0a.x, acA.x); acA.y = fmaf(e0, v0a.y, acA.y);
        acA.z = fmaf(e0, v0a.z, acA.z); acA.w = fmaf(e0, v0a.w, acA.w);
        acB.x = fmaf(e0, v0b.x, acB.x); acB.y = fmaf(e0, v0b.y, acB.y);
        acB.z = fmaf(e0, v0b.z, acB.z); acB.w = fmaf(e0, v0b.w, acB.w);
        acA.x = fmaf(e1, v1a.x, acA.x); acA.y = fmaf(e1, v1a.y, acA.y);
        acA.z = fmaf(e1, v1a.z, acA.z); acA.w = fmaf(e1, v1a.w, acA.w);
        acB.x = fmaf(e1, v1b.x, acB.x); acB.y = fmaf(e1, v1b.y, acB.y);
        acB.z = fmaf(e1, v1b.z, acB.z); acB.w = fmaf(e1, v1b.w, acB.w);
        den += e0 + e1;
    }
    if (i < en) {
        int2 pe = g_pair[i];
        uint4 t0 = *(const uint4*)(Trow + (size_t)pe.y * NPAD * DD);
        const float4* vp0 = (const float4*)(ego + (size_t)pe.x * DD + 8 * q);
        float4 v0a = vp0[0], v0b = vp0[1];
        float2 a00 = __bfloat1622float2(*(__nv_bfloat162*)&t0.x);
        float2 a01 = __bfloat1622float2(*(__nv_bfloat162*)&t0.y);
        float2 a02 = __bfloat1622float2(*(__nv_bfloat162*)&t0.z);
        float2 a03 = __bfloat1622float2(*(__nv_bfloat162*)&t0.w);
        float d0 = fmaf(a00.x, v0a.x, a00.y * v0a.y);
        d0 = fmaf(a01.x, v0a.z, d0); d0 = fmaf(a01.y, v0a.w, d0);
        d0 = fmaf(a02.x, v0b.x, d0); d0 = fmaf(a02.y, v0b.y, d0);
        d0 = fmaf(a03.x, v0b.z, d0); d0 = fmaf(a03.y, v0b.w, d0);
        #pragma unroll
        for (int o = 4; o; o >>= 1) d0 += __shfl_xor_sync(gm, d0, o);
        float s0 = d0 < 0.0f ? 0.01f * d0 : d0;
        float e0 = __expf(s0);
        acA.x = fmaf(e0, v0a.x, acA.x); acA.y = fmaf(e0, v0a.y, acA.y);
        acA.z = fmaf(e0, v0a.z, acA.z); acA.w = fmaf(e0, v0a.w, acA.w);
        acB.x = fmaf(e0, v0b.x, acB.x); acB.y = fmaf(e0, v0b.y, acB.y);
        acB.z = fmaf(e0, v0b.z, acB.z); acB.w = fmaf(e0, v0b.w, acB.w);
        den += e0;
    }

    float sc = cnt > 0 ? 1.0f / (den * (float)cnt) : 0.0f;
    float4* op = (float4*)(out + (size_t)node * DD + 8 * q);
    op[0] = make_float4(acA.x * sc, acA.y * sc, acA.z * sc, acA.w * sc);
    op[1] = make_float4(acB.x * sc, acB.y * sc, acB.z * sc, acB.w * sc);
}

// ---------------- launch: fork-join so GEMM overlaps scans + fill ----------------
extern "C" void kernel_launch(void* const* d_in, const int* in_sizes, int n_in,
                              void* d_out, int out_size) {
    const float* ego   = (const float*)d_in[0];
    const float* W     = (const float*)d_in[1];
    const int*   eidx  = (const int*)d_in[2];
    const int*   etype = (const int*)d_in[3];
    int N = in_sizes[0] / DD;
    int E = in_sizes[3];
    const int* head = eidx;
    const int* tail = eidx + E;
    float* out = (float*)d_out;

    // host-side resources created once (no device memory involved)
    static cudaStream_t s1 = nullptr;
    static cudaEvent_t evFork = nullptr, evJoin = nullptr;
    if (!s1) {
        cudaStreamCreateWithFlags(&s1, cudaStreamNonBlocking);
        cudaEventCreateWithFlags(&evFork, cudaEventDisableTiming);
        cudaEventCreateWithFlags(&evJoin, cudaEventDisableTiming);
    }

    int histb4 = (E + 1023) / 1024;          // 4 edges per thread
    int histb  = (E + 255) / 256;

    k_combo1<<<WCVTB + histb4, 256>>>(W, head, etype, E);

    // fork: GEMM (needs g_Wbf + g_rmask only) runs concurrently with scans/fill
    cudaEventRecord(evFork, 0);
    cudaStreamWaitEvent(s1, evFork, 0);
    k_gemm<<<SCANB, 256, 0, s1>>>(ego, N);
    cudaEventRecord(evJoin, s1);

    k_scan1<<<SCANB, 256>>>(N);
    k_scan23<<<SCANB, 256>>>(N, E);
    k_fill<<<histb, 256>>>(head, tail, etype, E);

    // join: fused needs both the CSR (stream 0) and T_all (s1)
    cudaStreamWaitEvent(0, evJoin, 0);
    int warps = (N + 3) / 4;
    k_fused<<<(warps * 32 + 255) / 256, 256>>>(ego, out, N);
}